// round 11
// baseline (speedup 1.0000x reference)
#include <cuda_runtime.h>
#include <cuda_bf16.h>
#include <cstdint>
#include <cstddef>

#define D_MODEL 1024
#define N_HEADS 16
#define BATCH   4
#define SEQ     4096
#define MTOK    (BATCH*SEQ)      /* 16384 tokens */
#define DK      64
#define BHD     (BATCH*N_HEADS)  /* 64 scan chains */

// ---------------- scratch (device globals: allocation-free) ----------------
__device__ float g_xn  [(size_t)MTOK*D_MODEL];
__device__ float g_q   [(size_t)MTOK*D_MODEL];   // [bh][t][dk]
__device__ float g_k   [(size_t)MTOK*D_MODEL];
__device__ float g_v   [(size_t)MTOK*D_MODEL];
__device__ float g_a   [(size_t)MTOK*D_MODEL];
__device__ float g_beta[(size_t)BHD*SEQ];
__device__ __nv_bfloat16 g_xnh[(size_t)MTOK*D_MODEL];  // xn hi/lo split
__device__ __nv_bfloat16 g_xnl[(size_t)MTOK*D_MODEL];
__device__ __nv_bfloat16 g_oh [(size_t)MTOK*D_MODEL];  // scan output hi/lo
__device__ __nv_bfloat16 g_ol [(size_t)MTOK*D_MODEL];
__device__ __nv_bfloat16 g_wth[(size_t)5*D_MODEL*D_MODEL]; // W^T hi (q,k,v,g,o)
__device__ __nv_bfloat16 g_wtl[(size_t)5*D_MODEL*D_MODEL]; // W^T lo

__device__ __forceinline__ float sigf(float x) { return 1.0f/(1.0f + __expf(-x)); }

__device__ __forceinline__ uint32_t smem_u32(const void* p) {
  uint32_t a;
  asm("{ .reg .u64 t; cvta.to.shared.u64 t, %1; cvt.u32.u64 %0, t; }" : "=r"(a) : "l"(p));
  return a;
}
__device__ __forceinline__ void ldsm4(uint32_t* r, uint32_t a) {
  asm volatile("ldmatrix.sync.aligned.m8n8.x4.shared.b16 {%0,%1,%2,%3}, [%4];"
    : "=r"(r[0]), "=r"(r[1]), "=r"(r[2]), "=r"(r[3]) : "r"(a));
}
__device__ __forceinline__ void mma_bf16(float* c, const uint32_t* a, const uint32_t* b) {
  asm volatile("mma.sync.aligned.m16n8k16.row.col.f32.bf16.bf16.f32 "
    "{%0,%1,%2,%3}, {%4,%5,%6,%7}, {%8,%9}, {%0,%1,%2,%3};"
    : "+f"(c[0]), "+f"(c[1]), "+f"(c[2]), "+f"(c[3])
    : "r"(a[0]), "r"(a[1]), "r"(a[2]), "r"(a[3]), "r"(b[0]), "r"(b[1]));
}
__device__ __forceinline__ void cpasync16(uint32_t dst, const void* src) {
  asm volatile("cp.async.ca.shared.global [%0], [%1], 16;" :: "r"(dst), "l"(src));
}
#define CP_COMMIT() asm volatile("cp.async.commit_group;" ::: "memory")
#define CP_WAIT1()  asm volatile("cp.async.wait_group 1;" ::: "memory")

// ---------------- LayerNorm: one block per token row (+ bf16 hi/lo split) ----------------
__global__ __launch_bounds__(256) void ln_kernel(const float* __restrict__ x,
                                                 const float* __restrict__ gamma,
                                                 const float* __restrict__ beta) {
  __shared__ float sred[9];
  int m = blockIdx.x, tid = threadIdx.x;
  const float4* xr = (const float4*)(x + (size_t)m*D_MODEL);
  float4 v = xr[tid];
  float s = v.x + v.y + v.z + v.w;
  #pragma unroll
  for (int o = 16; o > 0; o >>= 1) s += __shfl_xor_sync(0xffffffffu, s, o);
  if ((tid & 31) == 0) sred[tid >> 5] = s;
  __syncthreads();
  if (tid < 32) {
    float t2 = (tid < 8) ? sred[tid] : 0.f;
    #pragma unroll
    for (int o = 4; o > 0; o >>= 1) t2 += __shfl_xor_sync(0xffffffffu, t2, o);
    if (tid == 0) sred[8] = t2;
  }
  __syncthreads();
  float mean = sred[8] * (1.0f/1024.0f);
  float dx = v.x - mean, dy = v.y - mean, dz = v.z - mean, dw = v.w - mean;
  float sq = dx*dx + dy*dy + dz*dz + dw*dw;
  __syncthreads();
  #pragma unroll
  for (int o = 16; o > 0; o >>= 1) sq += __shfl_xor_sync(0xffffffffu, sq, o);
  if ((tid & 31) == 0) sred[tid >> 5] = sq;
  __syncthreads();
  if (tid < 32) {
    float t2 = (tid < 8) ? sred[tid] : 0.f;
    #pragma unroll
    for (int o = 4; o > 0; o >>= 1) t2 += __shfl_xor_sync(0xffffffffu, t2, o);
    if (tid == 0) sred[8] = t2;
  }
  __syncthreads();
  float inv = rsqrtf(sred[8] * (1.0f/1024.0f) + 1e-5f);
  float4 g  = ((const float4*)gamma)[tid];
  float4 bb = ((const float4*)beta)[tid];
  float4 o4;
  o4.x = dx*inv*g.x + bb.x;
  o4.y = dy*inv*g.y + bb.y;
  o4.z = dz*inv*g.z + bb.z;
  o4.w = dw*inv*g.w + bb.w;
  size_t base = (size_t)m*D_MODEL + tid*4;
  ((float4*)(g_xn + (size_t)m*D_MODEL))[tid] = o4;
  __nv_bfloat162 h0, h1, l0, l1;
  h0.x = __float2bfloat16(o4.x);  h0.y = __float2bfloat16(o4.y);
  h1.x = __float2bfloat16(o4.z);  h1.y = __float2bfloat16(o4.w);
  l0.x = __float2bfloat16(o4.x - __bfloat162float(h0.x));
  l0.y = __float2bfloat16(o4.y - __bfloat162float(h0.y));
  l1.x = __float2bfloat16(o4.z - __bfloat162float(h1.x));
  l1.y = __float2bfloat16(o4.w - __bfloat162float(h1.y));
  *(__nv_bfloat162*)(g_xnh + base)     = h0;
  *(__nv_bfloat162*)(g_xnh + base + 2) = h1;
  *(__nv_bfloat162*)(g_xnl + base)     = l0;
  *(__nv_bfloat162*)(g_xnl + base + 2) = l1;
}

// ---------------- weight prep: transpose [K][N] -> [N][K] + bf16 hi/lo split ----------------
// one launch, blockIdx.z selects the weight
__global__ __launch_bounds__(256) void wprep_kernel(const float* __restrict__ W0,
                                                    const float* __restrict__ W1,
                                                    const float* __restrict__ W2,
                                                    const float* __restrict__ W3,
                                                    const float* __restrict__ W4) {
  __shared__ float tile[32][33];
  int widx = blockIdx.z;
  const float* W = (widx == 0) ? W0 : (widx == 1) ? W1 : (widx == 2) ? W2 :
                   (widx == 3) ? W3 : W4;
  int bx = blockIdx.x, by = blockIdx.y;
  int tx = threadIdx.x & 31, ty = threadIdx.x >> 5;   // ty 0..7
  #pragma unroll
  for (int i = 0; i < 4; i++) {
    int a = ty + i*8;
    tile[a][tx] = W[(size_t)(by*32 + a)*D_MODEL + bx*32 + tx];
  }
  __syncthreads();
  __nv_bfloat16* dh = g_wth + (size_t)widx*D_MODEL*D_MODEL;
  __nv_bfloat16* dl = g_wtl + (size_t)widx*D_MODEL*D_MODEL;
  #pragma unroll
  for (int i = 0; i < 4; i++) {
    int a = ty + i*8;
    float v = tile[tx][a];                 // = W[by*32+tx][bx*32+a]
    __nv_bfloat16 h = __float2bfloat16(v);
    __nv_bfloat16 l = __float2bfloat16(v - __bfloat162float(h));
    size_t o = (size_t)(bx*32 + a)*D_MODEL + by*32 + tx;
    dh[o] = h;
    dl[o] = l;
  }
}

// ---------------- mma.sync bf16x3 GEMM: 128x128 tile, 4 warps (2x2, 64x64 each) ----------------
// Crossbar traffic per 32-K chunk: STS 40KB + LDS 64KB (vs 96KB with 2x4 layout).
// sel = base_sel + blockIdx.z.  sel 0..3: C = xn @ W_sel -> scatter (sel==3 sigmoid)
//                               sel 4  : C = o  @ Wo + x -> d_out token-major
#define KC    32
#define ASTR  40                      /* bf16 elems per SMEM row (80B, conflict-free ldmatrix) */
#define TELEM (128*ASTR)              /* 5120 bf16 per tile */
#define TBYTE (TELEM*2)               /* 10240 B */
#define GSMEM (2*4*TBYTE)             /* 81920 B dynamic */

__global__ __launch_bounds__(128, 2) void gemm_mma(int base_sel,
                                                   const float* __restrict__ xadd,
                                                   float* __restrict__ dout) {
  extern __shared__ __nv_bfloat16 smem[];
  int sel = base_sel + blockIdx.z;
  const __nv_bfloat16* Ahg = (sel == 4) ? g_oh : g_xnh;
  const __nv_bfloat16* Alg = (sel == 4) ? g_ol : g_xnl;
  const __nv_bfloat16* Bhg = g_wth + (size_t)sel*D_MODEL*D_MODEL;
  const __nv_bfloat16* Blg = g_wtl + (size_t)sel*D_MODEL*D_MODEL;

  int tid = threadIdx.x, lane = tid & 31, wid = tid >> 5;  // 4 warps
  int bn = blockIdx.x, bm = blockIdx.y;
  int m0 = bm*128, n0 = bn*128;
  int wm = wid >> 1, wn = wid & 1;          // warp tile: 64 (M) x 64 (N)
  uint32_t sbase = smem_u32(smem);

  float acc[4][8][4];
  #pragma unroll
  for (int i = 0; i < 4; i++)
    #pragma unroll
    for (int j = 0; j < 8; j++)
      #pragma unroll
      for (int u = 0; u < 4; u++) acc[i][j][u] = 0.f;

  // loader: thread = row, 4 consecutive 16B groups (64B contiguous per thread)
  auto LOADC = [&](int c, int b) {
    uint32_t dbase = sbase + b*4*TBYTE;
    int cc0 = c*KC;
    size_t ga = (size_t)(m0 + tid)*D_MODEL + cc0;
    size_t gb = (size_t)(n0 + tid)*D_MODEL + cc0;
    uint32_t so0 = (uint32_t)(tid*ASTR) * 2;
    #pragma unroll
    for (int i = 0; i < 4; i++) {
      uint32_t so = so0 + i*16;
      cpasync16(dbase + so,           Ahg + ga + i*8);
      cpasync16(dbase + TBYTE + so,   Alg + ga + i*8);
      cpasync16(dbase + 2*TBYTE + so, Bhg + gb + i*8);
      cpasync16(dbase + 3*TBYTE + so, Blg + gb + i*8);
    }
  };

  LOADC(0, 0); CP_COMMIT();
  LOADC(1, 1); CP_COMMIT();

  const int NC = D_MODEL/KC;   // 32
  #pragma unroll 1
  for (int c = 0; c < NC; c++) {
    CP_WAIT1();
    __syncthreads();

    uint32_t sA  = sbase + (c & 1)*4*TBYTE;
    uint32_t sAl = sA + TBYTE;
    uint32_t sBh = sA + 2*TBYTE;
    uint32_t sBl = sA + 3*TBYTE;

    #pragma unroll
    for (int kf = 0; kf < 2; kf++) {
      int ko = kf * 16;
      uint32_t ah[4][4], al[4][4];
      #pragma unroll
      for (int mt = 0; mt < 4; mt++) {
        int row = wm*64 + mt*16 + (lane & 15);
        uint32_t off = (uint32_t)(row*ASTR + ko + (lane >> 4)*8) * 2;
        ldsm4(ah[mt], sA + off);
        ldsm4(al[mt], sAl + off);
      }
      #pragma unroll
      for (int np = 0; np < 4; np++) {
        int quad = lane >> 3, l8 = lane & 7;
        int n = wn*64 + np*16 + ((quad & 2) << 2) + l8;
        int k = ko + (quad & 1)*8;
        uint32_t off = (uint32_t)(n*ASTR + k) * 2;
        uint32_t bh2[2][2], bl2[2][2];
        uint32_t t4[4];
        ldsm4(t4, sBh + off);
        bh2[0][0] = t4[0]; bh2[0][1] = t4[1];
        bh2[1][0] = t4[2]; bh2[1][1] = t4[3];
        ldsm4(t4, sBl + off);
        bl2[0][0] = t4[0]; bl2[0][1] = t4[1];
        bl2[1][0] = t4[2]; bl2[1][1] = t4[3];
        #pragma unroll
        for (int sub = 0; sub < 2; sub++) {
          int nt = np*2 + sub;
          #pragma unroll
          for (int mt = 0; mt < 4; mt++) {
            mma_bf16(acc[mt][nt], ah[mt], bh2[sub]);
            mma_bf16(acc[mt][nt], ah[mt], bl2[sub]);
            mma_bf16(acc[mt][nt], al[mt], bh2[sub]);
          }
        }
      }
    }
    __syncthreads();
    if (c + 2 < NC) { LOADC(c + 2, c & 1); CP_COMMIT(); }
  }

  // epilogue straight from fragment layout
  #pragma unroll
  for (int mt = 0; mt < 4; mt++) {
    #pragma unroll
    for (int nt = 0; nt < 8; nt++) {
      int mr = m0 + wm*64 + mt*16 + (lane >> 2);
      int nn = wn*64 + nt*8 + (lane & 3)*2;
      float* cc = acc[mt][nt];
      #pragma unroll
      for (int rs = 0; rs < 2; rs++) {
        int m = mr + rs*8;
        float2 v = make_float2(cc[rs*2], cc[rs*2 + 1]);
        if (sel < 4) {
          int ng = n0 + nn;
          int h = ng >> 6, e0 = ng & 63;
          int b = m >> 12, t = m & 4095;
          size_t base = ((size_t)(b*N_HEADS + h)*SEQ + t)*DK + e0;
          float* dst = (sel == 0) ? g_q : (sel == 1) ? g_k : (sel == 2) ? g_v : g_a;
          if (sel == 3) { v.x = sigf(v.x); v.y = sigf(v.y); }
          *(float2*)&dst[base] = v;
        } else {
          size_t off = (size_t)m*D_MODEL + n0 + nn;
          float2 x0 = *(const float2*)&xadd[off];
          *(float2*)&dout[off] = make_float2(v.x + x0.x, v.y + x0.y);
        }
      }
    }
  }
}

// ---------------- beta head v2: 128 tokens/block, Wb staged in 64KB smem ----------------
__global__ __launch_bounds__(128) void beta_kernel(const float* __restrict__ Wb) {
  extern __shared__ float wsh[];     // [1024][16] = 64KB
  int tid = threadIdx.x;
  // stage Wb: 4096 float4 by 128 threads = 32 each, coalesced
  #pragma unroll
  for (int i = 0; i < 32; i++) {
    int idx = i*128 + tid;
    ((float4*)wsh)[idx] = ((const float4*)Wb)[idx];
  }
  __syncthreads();

  int m = blockIdx.x*128 + tid;
  const float4* xrow = (const float4*)(g_xn + (size_t)m*D_MODEL);
  float p[16];
  #pragma unroll
  for (int h = 0; h < 16; h++) p[h] = 0.f;
  #pragma unroll 4
  for (int k4 = 0; k4 < 256; k4++) {
    float4 xv = xrow[k4];
    const float* w = wsh + k4*64;    // 4 rows of 16
    #pragma unroll
    for (int h = 0; h < 16; h += 4) {
      float4 w0 = *(const float4*)(w + h);
      float4 w1 = *(const float4*)(w + 16 + h);
      float4 w2 = *(const float4*)(w + 32 + h);
      float4 w3 = *(const float4*)(w + 48 + h);
      p[h+0] = fmaf(xv.x, w0.x, fmaf(xv.y, w1.x, fmaf(xv.z, w2.x, fmaf(xv.w, w3.x, p[h+0]))));
      p[h+1] = fmaf(xv.x, w0.y, fmaf(xv.y, w1.y, fmaf(xv.z, w2.y, fmaf(xv.w, w3.y, p[h+1]))));
      p[h+2] = fmaf(xv.x, w0.z, fmaf(xv.y, w1.z, fmaf(xv.z, w2.z, fmaf(xv.w, w3.z, p[h+2]))));
      p[h+3] = fmaf(xv.x, w0.w, fmaf(xv.y, w1.w, fmaf(xv.z, w2.w, fmaf(xv.w, w3.w, p[h+3]))));
    }
  }
  int b = m >> 12, t = m & 4095;
  #pragma unroll
  for (int h = 0; h < 16; h++)
    g_beta[(size_t)(b*N_HEADS + h)*SEQ + t] = sigf(p[h]);
}

// ---------------- delta-rule scan v3 ----------------
#define CH   16
#define SSTR 80   /* padded words per step: 4 quarters x 20 */

__global__ __launch_bounds__(128) void scan_kernel(float* __restrict__ sfin, int write_state) {
  int blk  = blockIdx.x;          // 0..127
  int bh   = blk >> 1;
  int part = blk & 1;
  int tid  = threadIdx.x;
  int col  = tid >> 2;            // 0..31
  int quarter = tid & 3;
  int d0   = quarter * 16;
  int e    = part * 32 + col;     // global column 0..63

  __shared__ float sk [2][CH*SSTR];   // k
  __shared__ float sak[2][CH*SSTR];   // a*k
  __shared__ float sqa[2][CH*SSTR];   // q*a
  __shared__ float sa [2][CH*SSTR];   // a
  __shared__ float sv [2][CH*32];
  __shared__ float sb [2][CH];
  __shared__ float sqk[2][CH];        // dot(q,k) per step

  int lidx = tid * 8;
  int lt   = lidx >> 6;               // step within chunk = tid>>3
  int ld   = lidx & 63;
  int sbase = lt*SSTR + (ld >> 4)*20 + (ld & 15);
  int vidx = tid * 4;
  int vt   = vidx >> 5;
  int vc   = vidx & 31;

  const size_t cb = (size_t)bh * SEQ * DK;
  const float* kp = g_k + cb + ld;
  const float* ap = g_a + cb + ld;
  const float* qp = g_q + cb + ld;
  const float* vp = g_v + cb + part*32 + vc;
  const float* bp = g_beta + (size_t)bh * SEQ;

  int b_idx = bh >> 4, h_idx = bh & 15;
  size_t obase = (size_t)b_idx * SEQ * D_MODEL + (size_t)h_idx * DK + e;

  float4 rk0, rk1, ra0, ra1, rq0, rq1, rv4;
  float rbv = 0.f;

  auto PREF = [&](int c) {
    size_t t0 = (size_t)(c*CH + lt) * DK;
    rk0 = *(const float4*)(kp + t0);  rk1 = *(const float4*)(kp + t0 + 4);
    ra0 = *(const float4*)(ap + t0);  ra1 = *(const float4*)(ap + t0 + 4);
    rq0 = *(const float4*)(qp + t0);  rq1 = *(const float4*)(qp + t0 + 4);
    rv4 = *(const float4*)(vp + (size_t)(c*CH + vt) * DK);
    if (tid < CH) rbv = bp[c*CH + tid];
  };
  auto STORE = [&](int b) {
    *(float4*)&sk[b][sbase]   = rk0;  *(float4*)&sk[b][sbase+4] = rk1;
    *(float4*)&sa[b][sbase]   = ra0;  *(float4*)&sa[b][sbase+4] = ra1;
    float4 p0 = make_float4(rk0.x*ra0.x, rk0.y*ra0.y, rk0.z*ra0.z, rk0.w*ra0.w);
    float4 p1 = make_float4(rk1.x*ra1.x, rk1.y*ra1.y, rk1.z*ra1.z, rk1.w*ra1.w);
    *(float4*)&sak[b][sbase]   = p0;  *(float4*)&sak[b][sbase+4] = p1;
    float4 u0 = make_float4(rq0.x*ra0.x, rq0.y*ra0.y, rq0.z*ra0.z, rq0.w*ra0.w);
    float4 u1 = make_float4(rq1.x*ra1.x, rq1.y*ra1.y, rq1.z*ra1.z, rq1.w*ra1.w);
    *(float4*)&sqa[b][sbase]   = u0;  *(float4*)&sqa[b][sbase+4] = u1;
    *(float4*)&sv[b][vt*32 + vc] = rv4;
    if (tid < CH) sb[b][tid] = rbv;
    float qk = rq0.x*rk0.x + rq0.y*rk0.y + rq0.z*rk0.z + rq0.w*rk0.w
             + rq1.x*rk1.x + rq1.y*rk1.y + rq1.z*rk1.z + rq1.w*rk1.w;
    qk += __shfl_xor_sync(0xffffffffu, qk, 1, 8);
    qk += __shfl_xor_sync(0xffffffffu, qk, 2, 8);
    qk += __shfl_xor_sync(0xffffffffu, qk, 4, 8);
    if ((tid & 7) == 0) sqk[b][lt] = qk;
  };

  float S[16];
  #pragma unroll
  for (int i = 0; i < 16; i++) S[i] = 0.f;

  PREF(0);
  STORE(0);
  __syncthreads();

  const int NCH = SEQ / CH;
  int qoff = quarter * 20;

  for (int c = 0; c < NCH; c++) {
    int buf = c & 1;
    if (c + 1 < NCH) PREF(c + 1);

    #pragma unroll 4
    for (int t = 0; t < CH; t++) {
      float bt = sb[buf][t];
      float vtv = sv[buf][t*32 + col];
      float qk = sqk[buf][t];
      int rb = t*SSTR + qoff;
      float kr[16], akr[16], qar[16];
      #pragma unroll
      for (int g = 0; g < 4; g++) {
        *(float4*)&kr[g*4]  = *(const float4*)&sk[buf][rb + g*4];
        *(float4*)&akr[g*4] = *(const float4*)&sak[buf][rb + g*4];
        *(float4*)&qar[g*4] = *(const float4*)&sqa[buf][rb + g*4];
      }
      float bv = bt * vtv;
      float rr[4] = {0.f, 0.f, 0.f, 0.f};
      float oo[4] = {0.f, 0.f, 0.f, 0.f};
      #pragma unroll
      for (int i = 0; i < 16; i++) {
        S[i] = fmaf(bv, kr[i], S[i]);
        rr[i & 3] = fmaf(akr[i], S[i], rr[i & 3]);
        oo[i & 3] = fmaf(qar[i], S[i], oo[i & 3]);
      }
      float r = (rr[0] + rr[1]) + (rr[2] + rr[3]);
      float oa = (oo[0] + oo[1]) + (oo[2] + oo[3]);
      float r1 = __shfl_xor_sync(0xffffffffu, r, 1);
      float o1 = __shfl_xor_sync(0xffffffffu, oa, 1);
      r += r1;  oa += o1;
      float r2 = __shfl_xor_sync(0xffffffffu, r, 2);
      float o2 = __shfl_xor_sync(0xffffffffu, oa, 2);
      r += r2;  oa += o2;
      float nbr = -bt * r;
      float ar[16];
      #pragma unroll
      for (int g = 0; g < 4; g++)
        *(float4*)&ar[g*4] = *(const float4*)&sa[buf][rb + g*4];
      #pragma unroll
      for (int i = 0; i < 16; i++)
        S[i] = fmaf(nbr, kr[i], ar[i] * S[i]);
      if (quarter == 0) {
        float o = fmaf(nbr, qk, oa);
        size_t oi = obase + (size_t)(c*CH + t) * D_MODEL;
        __nv_bfloat16 h = __float2bfloat16(o);
        g_oh[oi] = h;
        g_ol[oi] = __float2bfloat16(o - __bfloat162float(h));
      }
    }

    __syncthreads();
    if (c + 1 < NCH) STORE((c + 1) & 1);
    __syncthreads();
  }

  if (write_state) {
    #pragma unroll
    for (int i = 0; i < 16; i++)
      sfin[(size_t)bh*DK*DK + (size_t)(d0 + i)*DK + e] = S[i];
  }
}

// ---------------- launch ----------------
extern "C" void kernel_launch(void* const* d_in, const int* in_sizes, int n_in,
                              void* d_out, int out_size) {
  (void)in_sizes; (void)n_in;
  const float* x     = (const float*)d_in[0];
  const float* Wq    = (const float*)d_in[1];
  const float* Wk    = (const float*)d_in[2];
  const float* Wv    = (const float*)d_in[3];
  const float* Wg    = (const float*)d_in[4];
  const float* Wbeta = (const float*)d_in[5];
  const float* Wo    = (const float*)d_in[6];
  const float* gamma = (const float*)d_in[7];
  const float* bln   = (const float*)d_in[8];
  float* out = (float*)d_out;

  cudaFuncSetAttribute(gemm_mma, cudaFuncAttributeMaxDynamicSharedMemorySize, GSMEM);
  cudaFuncSetAttribute(beta_kernel, cudaFuncAttributeMaxDynamicSharedMemorySize, 65536);

  ln_kernel<<<MTOK, 256>>>(x, gamma, bln);

  dim3 wgrid(32, 32, 5);
  wprep_kernel<<<wgrid, 256>>>(Wq, Wk, Wv, Wg, Wo);

  dim3 pgrid(D_MODEL/128, MTOK/128, 4);   // all 4 projections in one launch
  gemm_mma<<<pgrid, 128, GSMEM>>>(0, nullptr, nullptr);
  beta_kernel<<<MTOK/128, 128, 65536>>>(Wbeta);

  int ws = (out_size >= MTOK*D_MODEL + BHD*DK*DK) ? 1 : 0;
  scan_kernel<<<2*BHD, 128>>>(out + (size_t)MTOK*D_MODEL, ws);

  dim3 ogrid(D_MODEL/128, MTOK/128, 1);
  gemm_mma<<<ogrid, 128, GSMEM>>>(4, x, out);
}

// round 12
// speedup vs baseline: 1.2763x; 1.2763x over previous
#include <cuda_runtime.h>
#include <cuda_bf16.h>
#include <cstdint>
#include <cstddef>

#define D_MODEL 1024
#define N_HEADS 16
#define BATCH   4
#define SEQ     4096
#define MTOK    (BATCH*SEQ)      /* 16384 tokens */
#define DK      64
#define BHD     (BATCH*N_HEADS)  /* 64 scan chains */

// ---------------- scratch (device globals: allocation-free) ----------------
__device__ float g_xn  [(size_t)MTOK*D_MODEL];
__device__ float g_q   [(size_t)MTOK*D_MODEL];   // [bh][t][dk]
__device__ float g_k   [(size_t)MTOK*D_MODEL];
__device__ float g_v   [(size_t)MTOK*D_MODEL];
__device__ float g_a   [(size_t)MTOK*D_MODEL];
__device__ float g_beta[(size_t)BHD*SEQ];
__device__ __nv_bfloat16 g_xnh[(size_t)MTOK*D_MODEL];  // xn hi/lo split
__device__ __nv_bfloat16 g_xnl[(size_t)MTOK*D_MODEL];
__device__ __nv_bfloat16 g_oh [(size_t)MTOK*D_MODEL];  // scan output hi/lo
__device__ __nv_bfloat16 g_ol [(size_t)MTOK*D_MODEL];
__device__ __nv_bfloat16 g_wth[(size_t)5*D_MODEL*D_MODEL]; // W^T hi (q,k,v,g,o)
__device__ __nv_bfloat16 g_wtl[(size_t)5*D_MODEL*D_MODEL]; // W^T lo

__device__ __forceinline__ float sigf(float x) { return 1.0f/(1.0f + __expf(-x)); }

__device__ __forceinline__ uint32_t smem_u32(const void* p) {
  uint32_t a;
  asm("{ .reg .u64 t; cvta.to.shared.u64 t, %1; cvt.u32.u64 %0, t; }" : "=r"(a) : "l"(p));
  return a;
}
__device__ __forceinline__ void ldsm4(uint32_t* r, uint32_t a) {
  asm volatile("ldmatrix.sync.aligned.m8n8.x4.shared.b16 {%0,%1,%2,%3}, [%4];"
    : "=r"(r[0]), "=r"(r[1]), "=r"(r[2]), "=r"(r[3]) : "r"(a));
}
__device__ __forceinline__ void mma_bf16(float* c, const uint32_t* a, const uint32_t* b) {
  asm volatile("mma.sync.aligned.m16n8k16.row.col.f32.bf16.bf16.f32 "
    "{%0,%1,%2,%3}, {%4,%5,%6,%7}, {%8,%9}, {%0,%1,%2,%3};"
    : "+f"(c[0]), "+f"(c[1]), "+f"(c[2]), "+f"(c[3])
    : "r"(a[0]), "r"(a[1]), "r"(a[2]), "r"(a[3]), "r"(b[0]), "r"(b[1]));
}
__device__ __forceinline__ void cpasync16(uint32_t dst, const void* src) {
  asm volatile("cp.async.ca.shared.global [%0], [%1], 16;" :: "r"(dst), "l"(src));
}
#define CP_COMMIT() asm volatile("cp.async.commit_group;" ::: "memory")
#define CP_WAIT1()  asm volatile("cp.async.wait_group 1;" ::: "memory")

// ---------------- LayerNorm: one block per token row (+ bf16 hi/lo split) ----------------
__global__ __launch_bounds__(256) void ln_kernel(const float* __restrict__ x,
                                                 const float* __restrict__ gamma,
                                                 const float* __restrict__ beta) {
  __shared__ float sred[9];
  int m = blockIdx.x, tid = threadIdx.x;
  const float4* xr = (const float4*)(x + (size_t)m*D_MODEL);
  float4 v = xr[tid];
  float s = v.x + v.y + v.z + v.w;
  #pragma unroll
  for (int o = 16; o > 0; o >>= 1) s += __shfl_xor_sync(0xffffffffu, s, o);
  if ((tid & 31) == 0) sred[tid >> 5] = s;
  __syncthreads();
  if (tid < 32) {
    float t2 = (tid < 8) ? sred[tid] : 0.f;
    #pragma unroll
    for (int o = 4; o > 0; o >>= 1) t2 += __shfl_xor_sync(0xffffffffu, t2, o);
    if (tid == 0) sred[8] = t2;
  }
  __syncthreads();
  float mean = sred[8] * (1.0f/1024.0f);
  float dx = v.x - mean, dy = v.y - mean, dz = v.z - mean, dw = v.w - mean;
  float sq = dx*dx + dy*dy + dz*dz + dw*dw;
  __syncthreads();
  #pragma unroll
  for (int o = 16; o > 0; o >>= 1) sq += __shfl_xor_sync(0xffffffffu, sq, o);
  if ((tid & 31) == 0) sred[tid >> 5] = sq;
  __syncthreads();
  if (tid < 32) {
    float t2 = (tid < 8) ? sred[tid] : 0.f;
    #pragma unroll
    for (int o = 4; o > 0; o >>= 1) t2 += __shfl_xor_sync(0xffffffffu, t2, o);
    if (tid == 0) sred[8] = t2;
  }
  __syncthreads();
  float inv = rsqrtf(sred[8] * (1.0f/1024.0f) + 1e-5f);
  float4 g  = ((const float4*)gamma)[tid];
  float4 bb = ((const float4*)beta)[tid];
  float4 o4;
  o4.x = dx*inv*g.x + bb.x;
  o4.y = dy*inv*g.y + bb.y;
  o4.z = dz*inv*g.z + bb.z;
  o4.w = dw*inv*g.w + bb.w;
  size_t base = (size_t)m*D_MODEL + tid*4;
  ((float4*)(g_xn + (size_t)m*D_MODEL))[tid] = o4;
  __nv_bfloat162 h0, h1, l0, l1;
  h0.x = __float2bfloat16(o4.x);  h0.y = __float2bfloat16(o4.y);
  h1.x = __float2bfloat16(o4.z);  h1.y = __float2bfloat16(o4.w);
  l0.x = __float2bfloat16(o4.x - __bfloat162float(h0.x));
  l0.y = __float2bfloat16(o4.y - __bfloat162float(h0.y));
  l1.x = __float2bfloat16(o4.z - __bfloat162float(h1.x));
  l1.y = __float2bfloat16(o4.w - __bfloat162float(h1.y));
  *(__nv_bfloat162*)(g_xnh + base)     = h0;
  *(__nv_bfloat162*)(g_xnh + base + 2) = h1;
  *(__nv_bfloat162*)(g_xnl + base)     = l0;
  *(__nv_bfloat162*)(g_xnl + base + 2) = l1;
}

// ---------------- weight prep: transpose [K][N] -> [N][K] + bf16 hi/lo split ----------------
// one launch, blockIdx.z selects the weight
__global__ __launch_bounds__(256) void wprep_kernel(const float* __restrict__ W0,
                                                    const float* __restrict__ W1,
                                                    const float* __restrict__ W2,
                                                    const float* __restrict__ W3,
                                                    const float* __restrict__ W4) {
  __shared__ float tile[32][33];
  int widx = blockIdx.z;
  const float* W = (widx == 0) ? W0 : (widx == 1) ? W1 : (widx == 2) ? W2 :
                   (widx == 3) ? W3 : W4;
  int bx = blockIdx.x, by = blockIdx.y;
  int tx = threadIdx.x & 31, ty = threadIdx.x >> 5;   // ty 0..7
  #pragma unroll
  for (int i = 0; i < 4; i++) {
    int a = ty + i*8;
    tile[a][tx] = W[(size_t)(by*32 + a)*D_MODEL + bx*32 + tx];
  }
  __syncthreads();
  __nv_bfloat16* dh = g_wth + (size_t)widx*D_MODEL*D_MODEL;
  __nv_bfloat16* dl = g_wtl + (size_t)widx*D_MODEL*D_MODEL;
  #pragma unroll
  for (int i = 0; i < 4; i++) {
    int a = ty + i*8;
    float v = tile[tx][a];                 // = W[by*32+tx][bx*32+a]
    __nv_bfloat16 h = __float2bfloat16(v);
    __nv_bfloat16 l = __float2bfloat16(v - __bfloat162float(h));
    size_t o = (size_t)(bx*32 + a)*D_MODEL + by*32 + tx;
    dh[o] = h;
    dl[o] = l;
  }
}

// ---------------- mma.sync bf16x3 GEMM: 128x128 tile, 8 warps (2x4), cp.async pipeline ----------------
// (Round-10 configuration: measured best. 256 thr, 2 CTAs/SM.)
// sel = base_sel + blockIdx.z.  sel 0..3: C = xn @ W_sel -> scatter (sel==3 sigmoid)
//                               sel 4  : C = o  @ Wo + x -> d_out token-major
#define KC    32
#define ASTR  40                      /* bf16 elems per SMEM row (80B, conflict-free ldmatrix) */
#define TELEM (128*ASTR)              /* 5120 bf16 per tile */
#define TBYTE (TELEM*2)               /* 10240 B */
#define GSMEM (2*4*TBYTE)             /* 81920 B dynamic */

__global__ __launch_bounds__(256, 2) void gemm_mma(int base_sel,
                                                   const float* __restrict__ xadd,
                                                   float* __restrict__ dout) {
  extern __shared__ __nv_bfloat16 smem[];
  int sel = base_sel + blockIdx.z;
  const __nv_bfloat16* Ahg = (sel == 4) ? g_oh : g_xnh;
  const __nv_bfloat16* Alg = (sel == 4) ? g_ol : g_xnl;
  const __nv_bfloat16* Bhg = g_wth + (size_t)sel*D_MODEL*D_MODEL;
  const __nv_bfloat16* Blg = g_wtl + (size_t)sel*D_MODEL*D_MODEL;

  int tid = threadIdx.x, lane = tid & 31, wid = tid >> 5;
  int bn = blockIdx.x, bm = blockIdx.y;
  int m0 = bm*128, n0 = bn*128;
  int wm = wid >> 2, wn = wid & 3;          // warp tile: 64 (M) x 32 (N)
  uint32_t sbase = smem_u32(smem);

  float acc[4][4][4];
  #pragma unroll
  for (int i = 0; i < 4; i++)
    #pragma unroll
    for (int j = 0; j < 4; j++)
      #pragma unroll
      for (int u = 0; u < 4; u++) acc[i][j][u] = 0.f;

  // loader: thread covers row lr, two 8-elem groups at lc0, lc0+8
  int lr  = tid >> 1;
  int lc0 = (tid & 1) * 16;

  auto LOADC = [&](int c, int b) {
    uint32_t dbase = sbase + b*4*TBYTE;
    #pragma unroll
    for (int i = 0; i < 2; i++) {
      int cc = c*KC + lc0 + i*8;
      size_t ga = (size_t)(m0 + lr)*D_MODEL + cc;
      size_t gb = (size_t)(n0 + lr)*D_MODEL + cc;
      uint32_t so = (uint32_t)(lr*ASTR + lc0 + i*8) * 2;
      cpasync16(dbase + so,           Ahg + ga);
      cpasync16(dbase + TBYTE + so,   Alg + ga);
      cpasync16(dbase + 2*TBYTE + so, Bhg + gb);
      cpasync16(dbase + 3*TBYTE + so, Blg + gb);
    }
  };

  LOADC(0, 0); CP_COMMIT();
  LOADC(1, 1); CP_COMMIT();

  const int NC = D_MODEL/KC;   // 32
  #pragma unroll 1
  for (int c = 0; c < NC; c++) {
    CP_WAIT1();
    __syncthreads();

    uint32_t sA  = sbase + (c & 1)*4*TBYTE;
    uint32_t sAl = sA + TBYTE;
    uint32_t sBh = sA + 2*TBYTE;
    uint32_t sBl = sA + 3*TBYTE;

    #pragma unroll
    for (int kf = 0; kf < 2; kf++) {
      int ko = kf * 16;
      uint32_t ah[4][4], al[4][4], bh[4][2], bl[4][2];
      #pragma unroll
      for (int mt = 0; mt < 4; mt++) {
        int row = wm*64 + mt*16 + (lane & 15);
        uint32_t off = (uint32_t)(row*ASTR + ko + (lane >> 4)*8) * 2;
        ldsm4(ah[mt], sA + off);
        ldsm4(al[mt], sAl + off);
      }
      #pragma unroll
      for (int np = 0; np < 2; np++) {
        int quad = lane >> 3, l8 = lane & 7;
        int n = wn*32 + np*16 + ((quad & 2) << 2) + l8;
        int k = ko + (quad & 1)*8;
        uint32_t off = (uint32_t)(n*ASTR + k) * 2;
        uint32_t t4[4];
        ldsm4(t4, sBh + off);
        bh[np*2][0] = t4[0]; bh[np*2][1] = t4[1];
        bh[np*2+1][0] = t4[2]; bh[np*2+1][1] = t4[3];
        ldsm4(t4, sBl + off);
        bl[np*2][0] = t4[0]; bl[np*2][1] = t4[1];
        bl[np*2+1][0] = t4[2]; bl[np*2+1][1] = t4[3];
      }
      #pragma unroll
      for (int mt = 0; mt < 4; mt++)
        #pragma unroll
        for (int nt = 0; nt < 4; nt++) {
          mma_bf16(acc[mt][nt], ah[mt], bh[nt]);
          mma_bf16(acc[mt][nt], ah[mt], bl[nt]);
          mma_bf16(acc[mt][nt], al[mt], bh[nt]);
        }
    }
    __syncthreads();
    if (c + 2 < NC) { LOADC(c + 2, c & 1); CP_COMMIT(); }
  }

  // epilogue straight from fragment layout: c0,c1 @ (row, col..col+1); c2,c3 @ row+8
  #pragma unroll
  for (int mt = 0; mt < 4; mt++) {
    #pragma unroll
    for (int nt = 0; nt < 4; nt++) {
      int mr = m0 + wm*64 + mt*16 + (lane >> 2);
      int nn = wn*32 + nt*8 + (lane & 3)*2;
      float* cc = acc[mt][nt];
      #pragma unroll
      for (int rs = 0; rs < 2; rs++) {
        int m = mr + rs*8;
        float2 v = make_float2(cc[rs*2], cc[rs*2 + 1]);
        if (sel < 4) {
          int ng = n0 + nn;
          int h = ng >> 6, e0 = ng & 63;
          int b = m >> 12, t = m & 4095;
          size_t base = ((size_t)(b*N_HEADS + h)*SEQ + t)*DK + e0;
          float* dst = (sel == 0) ? g_q : (sel == 1) ? g_k : (sel == 2) ? g_v : g_a;
          if (sel == 3) { v.x = sigf(v.x); v.y = sigf(v.y); }
          *(float2*)&dst[base] = v;
        } else {
          size_t off = (size_t)m*D_MODEL + n0 + nn;
          float2 x0 = *(const float2*)&xadd[off];
          *(float2*)&dout[off] = make_float2(v.x + x0.x, v.y + x0.y);
        }
      }
    }
  }
}

// ---------------- beta head v2: 128 tokens/block, Wb staged in 64KB smem ----------------
__global__ __launch_bounds__(128) void beta_kernel(const float* __restrict__ Wb) {
  extern __shared__ float wsh[];     // [1024][16] = 64KB
  int tid = threadIdx.x;
  #pragma unroll
  for (int i = 0; i < 32; i++) {
    int idx = i*128 + tid;
    ((float4*)wsh)[idx] = ((const float4*)Wb)[idx];
  }
  __syncthreads();

  int m = blockIdx.x*128 + tid;
  const float4* xrow = (const float4*)(g_xn + (size_t)m*D_MODEL);
  float p[16];
  #pragma unroll
  for (int h = 0; h < 16; h++) p[h] = 0.f;
  #pragma unroll 4
  for (int k4 = 0; k4 < 256; k4++) {
    float4 xv = xrow[k4];
    const float* w = wsh + k4*64;    // 4 rows of 16
    #pragma unroll
    for (int h = 0; h < 16; h += 4) {
      float4 w0 = *(const float4*)(w + h);
      float4 w1 = *(const float4*)(w + 16 + h);
      float4 w2 = *(const float4*)(w + 32 + h);
      float4 w3 = *(const float4*)(w + 48 + h);
      p[h+0] = fmaf(xv.x, w0.x, fmaf(xv.y, w1.x, fmaf(xv.z, w2.x, fmaf(xv.w, w3.x, p[h+0]))));
      p[h+1] = fmaf(xv.x, w0.y, fmaf(xv.y, w1.y, fmaf(xv.z, w2.y, fmaf(xv.w, w3.y, p[h+1]))));
      p[h+2] = fmaf(xv.x, w0.z, fmaf(xv.y, w1.z, fmaf(xv.z, w2.z, fmaf(xv.w, w3.z, p[h+2]))));
      p[h+3] = fmaf(xv.x, w0.w, fmaf(xv.y, w1.w, fmaf(xv.z, w2.w, fmaf(xv.w, w3.w, p[h+3]))));
    }
  }
  int b = m >> 12, t = m & 4095;
  #pragma unroll
  for (int h = 0; h < 16; h++)
    g_beta[(size_t)(b*N_HEADS + h)*SEQ + t] = sigf(p[h]);
}

// ---------------- delta-rule scan v3 ----------------
#define CH   16
#define SSTR 80   /* padded words per step: 4 quarters x 20 */

__global__ __launch_bounds__(128) void scan_kernel(float* __restrict__ sfin, int write_state) {
  int blk  = blockIdx.x;          // 0..127
  int bh   = blk >> 1;
  int part = blk & 1;
  int tid  = threadIdx.x;
  int col  = tid >> 2;            // 0..31
  int quarter = tid & 3;
  int d0   = quarter * 16;
  int e    = part * 32 + col;     // global column 0..63

  __shared__ float sk [2][CH*SSTR];   // k
  __shared__ float sak[2][CH*SSTR];   // a*k
  __shared__ float sqa[2][CH*SSTR];   // q*a
  __shared__ float sa [2][CH*SSTR];   // a
  __shared__ float sv [2][CH*32];
  __shared__ float sb [2][CH];
  __shared__ float sqk[2][CH];        // dot(q,k) per step

  int lidx = tid * 8;
  int lt   = lidx >> 6;               // step within chunk = tid>>3
  int ld   = lidx & 63;
  int sbase = lt*SSTR + (ld >> 4)*20 + (ld & 15);
  int vidx = tid * 4;
  int vt   = vidx >> 5;
  int vc   = vidx & 31;

  const size_t cb = (size_t)bh * SEQ * DK;
  const float* kp = g_k + cb + ld;
  const float* ap = g_a + cb + ld;
  const float* qp = g_q + cb + ld;
  const float* vp = g_v + cb + part*32 + vc;
  const float* bp = g_beta + (size_t)bh * SEQ;

  int b_idx = bh >> 4, h_idx = bh & 15;
  size_t obase = (size_t)b_idx * SEQ * D_MODEL + (size_t)h_idx * DK + e;

  float4 rk0, rk1, ra0, ra1, rq0, rq1, rv4;
  float rbv = 0.f;

  auto PREF = [&](int c) {
    size_t t0 = (size_t)(c*CH + lt) * DK;
    rk0 = *(const float4*)(kp + t0);  rk1 = *(const float4*)(kp + t0 + 4);
    ra0 = *(const float4*)(ap + t0);  ra1 = *(const float4*)(ap + t0 + 4);
    rq0 = *(const float4*)(qp + t0);  rq1 = *(const float4*)(qp + t0 + 4);
    rv4 = *(const float4*)(vp + (size_t)(c*CH + vt) * DK);
    if (tid < CH) rbv = bp[c*CH + tid];
  };
  auto STORE = [&](int b) {
    *(float4*)&sk[b][sbase]   = rk0;  *(float4*)&sk[b][sbase+4] = rk1;
    *(float4*)&sa[b][sbase]   = ra0;  *(float4*)&sa[b][sbase+4] = ra1;
    float4 p0 = make_float4(rk0.x*ra0.x, rk0.y*ra0.y, rk0.z*ra0.z, rk0.w*ra0.w);
    float4 p1 = make_float4(rk1.x*ra1.x, rk1.y*ra1.y, rk1.z*ra1.z, rk1.w*ra1.w);
    *(float4*)&sak[b][sbase]   = p0;  *(float4*)&sak[b][sbase+4] = p1;
    float4 u0 = make_float4(rq0.x*ra0.x, rq0.y*ra0.y, rq0.z*ra0.z, rq0.w*ra0.w);
    float4 u1 = make_float4(rq1.x*ra1.x, rq1.y*ra1.y, rq1.z*ra1.z, rq1.w*ra1.w);
    *(float4*)&sqa[b][sbase]   = u0;  *(float4*)&sqa[b][sbase+4] = u1;
    *(float4*)&sv[b][vt*32 + vc] = rv4;
    if (tid < CH) sb[b][tid] = rbv;
    float qk = rq0.x*rk0.x + rq0.y*rk0.y + rq0.z*rk0.z + rq0.w*rk0.w
             + rq1.x*rk1.x + rq1.y*rk1.y + rq1.z*rk1.z + rq1.w*rk1.w;
    qk += __shfl_xor_sync(0xffffffffu, qk, 1, 8);
    qk += __shfl_xor_sync(0xffffffffu, qk, 2, 8);
    qk += __shfl_xor_sync(0xffffffffu, qk, 4, 8);
    if ((tid & 7) == 0) sqk[b][lt] = qk;
  };

  float S[16];
  #pragma unroll
  for (int i = 0; i < 16; i++) S[i] = 0.f;

  PREF(0);
  STORE(0);
  __syncthreads();

  const int NCH = SEQ / CH;
  int qoff = quarter * 20;

  for (int c = 0; c < NCH; c++) {
    int buf = c & 1;
    if (c + 1 < NCH) PREF(c + 1);

    #pragma unroll 4
    for (int t = 0; t < CH; t++) {
      float bt = sb[buf][t];
      float vtv = sv[buf][t*32 + col];
      float qk = sqk[buf][t];
      int rb = t*SSTR + qoff;
      float kr[16], akr[16], qar[16];
      #pragma unroll
      for (int g = 0; g < 4; g++) {
        *(float4*)&kr[g*4]  = *(const float4*)&sk[buf][rb + g*4];
        *(float4*)&akr[g*4] = *(const float4*)&sak[buf][rb + g*4];
        *(float4*)&qar[g*4] = *(const float4*)&sqa[buf][rb + g*4];
      }
      float bv = bt * vtv;
      float rr[4] = {0.f, 0.f, 0.f, 0.f};
      float oo[4] = {0.f, 0.f, 0.f, 0.f};
      #pragma unroll
      for (int i = 0; i < 16; i++) {
        S[i] = fmaf(bv, kr[i], S[i]);
        rr[i & 3] = fmaf(akr[i], S[i], rr[i & 3]);
        oo[i & 3] = fmaf(qar[i], S[i], oo[i & 3]);
      }
      float r = (rr[0] + rr[1]) + (rr[2] + rr[3]);
      float oa = (oo[0] + oo[1]) + (oo[2] + oo[3]);
      float r1 = __shfl_xor_sync(0xffffffffu, r, 1);
      float o1 = __shfl_xor_sync(0xffffffffu, oa, 1);
      r += r1;  oa += o1;
      float r2 = __shfl_xor_sync(0xffffffffu, r, 2);
      float o2 = __shfl_xor_sync(0xffffffffu, oa, 2);
      r += r2;  oa += o2;
      float nbr = -bt * r;
      float ar[16];
      #pragma unroll
      for (int g = 0; g < 4; g++)
        *(float4*)&ar[g*4] = *(const float4*)&sa[buf][rb + g*4];
      #pragma unroll
      for (int i = 0; i < 16; i++)
        S[i] = fmaf(nbr, kr[i], ar[i] * S[i]);
      if (quarter == 0) {
        float o = fmaf(nbr, qk, oa);
        size_t oi = obase + (size_t)(c*CH + t) * D_MODEL;
        __nv_bfloat16 h = __float2bfloat16(o);
        g_oh[oi] = h;
        g_ol[oi] = __float2bfloat16(o - __bfloat162float(h));
      }
    }

    __syncthreads();
    if (c + 1 < NCH) STORE((c + 1) & 1);
    __syncthreads();
  }

  if (write_state) {
    #pragma unroll
    for (int i = 0; i < 16; i++)
      sfin[(size_t)bh*DK*DK + (size_t)(d0 + i)*DK + e] = S[i];
  }
}

// ---------------- launch ----------------
extern "C" void kernel_launch(void* const* d_in, const int* in_sizes, int n_in,
                              void* d_out, int out_size) {
  (void)in_sizes; (void)n_in;
  const float* x     = (const float*)d_in[0];
  const float* Wq    = (const float*)d_in[1];
  const float* Wk    = (const float*)d_in[2];
  const float* Wv    = (const float*)d_in[3];
  const float* Wg    = (const float*)d_in[4];
  const float* Wbeta = (const float*)d_in[5];
  const float* Wo    = (const float*)d_in[6];
  const float* gamma = (const float*)d_in[7];
  const float* bln   = (const float*)d_in[8];
  float* out = (float*)d_out;

  cudaFuncSetAttribute(gemm_mma, cudaFuncAttributeMaxDynamicSharedMemorySize, GSMEM);
  cudaFuncSetAttribute(beta_kernel, cudaFuncAttributeMaxDynamicSharedMemorySize, 65536);

  ln_kernel<<<MTOK, 256>>>(x, gamma, bln);

  dim3 wgrid(32, 32, 5);
  wprep_kernel<<<wgrid, 256>>>(Wq, Wk, Wv, Wg, Wo);

  dim3 pgrid(D_MODEL/128, MTOK/128, 4);   // all 4 projections in one launch
  gemm_mma<<<pgrid, 256, GSMEM>>>(0, nullptr, nullptr);
  beta_kernel<<<MTOK/128, 128, 65536>>>(Wbeta);

  int ws = (out_size >= MTOK*D_MODEL + BHD*DK*DK) ? 1 : 0;
  scan_kernel<<<2*BHD, 128>>>(out + (size_t)MTOK*D_MODEL, ws);

  dim3 ogrid(D_MODEL/128, MTOK/128, 1);
  gemm_mma<<<ogrid, 256, GSMEM>>>(4, x, out);
}